// round 2
// baseline (speedup 1.0000x reference)
#include <cuda_runtime.h>

#define Bn 8
#define Tn 100
#define BT 800
#define Nn 100000
#define MARGINF 0.1f
#define THRESHF 0.5f
#define BIGV 1000000000.0f
#define CHUNK 256
#define NBLK 296

__device__ float g_r[BT * 3];             // retrajs, [bt][3]
__device__ float g_lo[Bn * 3];            // box lower per (b,e)
__device__ float g_hi[Bn * 3];            // box upper per (b,e)
__device__ float4 g_pts[Nn];              // {x,y,z,rad}
__device__ unsigned char g_mask[Nn];      // bit b = inside box b
__device__ unsigned int g_minkey[BT];     // float-ordered min keys

__device__ __forceinline__ unsigned int fkey(float f) {
    unsigned int u = __float_as_uint(f);
    return (u & 0x80000000u) ? ~u : (u | 0x80000000u);
}
__device__ __forceinline__ float fdec(unsigned int k) {
    unsigned int u = (k & 0x80000000u) ? (k ^ 0x80000000u) : ~k;
    return __uint_as_float(u);
}

// ---------------------------------------------------------------------------
// Kernel A: retrajs[bt] = ss[b] * (outputs[bt] @ c2w[b][:3,:3]^T_row) + trans,
// per-b bounding boxes +/- thres, init min keys. One block.
// ---------------------------------------------------------------------------
__global__ void kA(const float* __restrict__ outputs,
                   const float* __restrict__ c2ws,
                   const float* __restrict__ scene_scales) {
    __shared__ float s_r[BT * 3];
    int tid = threadIdx.x;

    if (tid < BT) {
        int b = tid / Tn;
        float ss = scene_scales[b];
        float o0 = outputs[tid * 3 + 0];
        float o1 = outputs[tid * 3 + 1];
        float o2 = outputs[tid * 3 + 2];
        const float* c = c2ws + b * 16;
#pragma unroll
        for (int e = 0; e < 3; e++) {
            float dot = o0 * c[e * 4 + 0] + o1 * c[e * 4 + 1] + o2 * c[e * 4 + 2];
            float r = ss * dot + c[e * 4 + 3];
            s_r[tid * 3 + e] = r;
            g_r[tid * 3 + e] = r;
        }
        g_minkey[tid] = fkey(BIGV);
    }
    __syncthreads();

    if (tid < Bn * 3) {
        int b = tid / 3;
        int e = tid % 3;
        float lo = 3.4e38f, hi = -3.4e38f;
        for (int t = 0; t < Tn; t++) {
            float v = s_r[(b * Tn + t) * 3 + e];
            lo = fminf(lo, v);
            hi = fmaxf(hi, v);
        }
        float thres = THRESHF * scene_scales[0];
        g_lo[tid] = lo - thres;
        g_hi[tid] = hi + thres;
    }
}

// ---------------------------------------------------------------------------
// Kernel B: pack points {x,y,z,rad=max(scales)} and per-b inside bitmask.
// ---------------------------------------------------------------------------
__global__ void kB(const float* __restrict__ means,
                   const float* __restrict__ scales) {
    __shared__ float slo[Bn * 3];
    __shared__ float shi[Bn * 3];
    if (threadIdx.x < Bn * 3) {
        slo[threadIdx.x] = g_lo[threadIdx.x];
        shi[threadIdx.x] = g_hi[threadIdx.x];
    }
    __syncthreads();

    int n = blockIdx.x * blockDim.x + threadIdx.x;
    if (n >= Nn) return;

    float mx = means[n * 3 + 0];
    float my = means[n * 3 + 1];
    float mz = means[n * 3 + 2];
    float s0 = scales[n * 3 + 0];
    float s1 = scales[n * 3 + 1];
    float s2 = scales[n * 3 + 2];
    float rad = fmaxf(s0, fmaxf(s1, s2));

    unsigned int msk = 0;
#pragma unroll
    for (int b = 0; b < Bn; b++) {
        bool in = (mx >= slo[b * 3 + 0]) & (mx <= shi[b * 3 + 0]) &
                  (my >= slo[b * 3 + 1]) & (my <= shi[b * 3 + 1]) &
                  (mz >= slo[b * 3 + 2]) & (mz <= shi[b * 3 + 2]);
        msk |= (in ? 1u : 0u) << b;
    }
    g_pts[n] = make_float4(mx, my, mz, rad);
    g_mask[n] = (unsigned char)msk;
}

// ---------------------------------------------------------------------------
// Kernel C: main. 800 threads/block (thread = one (b,t) pair), each block
// owns a contiguous slice of n, staged through SMEM in CHUNK pieces.
// Thread keeps running min(dist - rad) over inside points.
// ---------------------------------------------------------------------------
__global__ void __launch_bounds__(BT, 2) kC() {
    __shared__ float4 sp[CHUNK];
    __shared__ unsigned char sm[CHUNK];

    int tid = threadIdx.x;
    int per = (Nn + gridDim.x - 1) / gridDim.x;
    int n0 = blockIdx.x * per;
    int n1 = min(Nn, n0 + per);

    float rx = g_r[tid * 3 + 0];
    float ry = g_r[tid * 3 + 1];
    float rz = g_r[tid * 3 + 2];
    unsigned int bbit = 1u << (tid / Tn);
    float m = BIGV;

    for (int c0 = n0; c0 < n1; c0 += CHUNK) {
        int cnt = min(CHUNK, n1 - c0);
        __syncthreads();
        for (int i = tid; i < cnt; i += BT) {
            sp[i] = g_pts[c0 + i];
            sm[i] = g_mask[c0 + i];
        }
        __syncthreads();

#pragma unroll 4
        for (int i = 0; i < cnt; i++) {
            unsigned int msk = sm[i];
            if (msk & bbit) {
                float4 p = sp[i];
                float dx = rx - p.x;
                float dy = ry - p.y;
                float dz = rz - p.z;
                float d2 = fmaf(dx, dx, fmaf(dy, dy, dz * dz));
                float d;
                asm("sqrt.approx.f32 %0, %1;" : "=f"(d) : "f"(d2));
                m = fminf(m, d - p.w);
            }
        }
    }

    atomicMin(&g_minkey[tid], fkey(m));
}

// ---------------------------------------------------------------------------
// Kernel D: out = sum_bt relu(MARGIN - m_bt) / (B*T). One block.
// ---------------------------------------------------------------------------
__global__ void kD(float* __restrict__ out) {
    __shared__ float ssum[1024];
    int tid = threadIdx.x;
    float v = 0.0f;
    if (tid < BT) {
        float m = fdec(g_minkey[tid]);
        v = fmaxf(0.0f, MARGINF - m);   // relu(-(m - MARGIN))
    }
    ssum[tid] = v;
    __syncthreads();
#pragma unroll
    for (int s = 512; s > 0; s >>= 1) {
        if (tid < s) ssum[tid] += ssum[tid + s];
        __syncthreads();
    }
    if (tid == 0) out[0] = ssum[0] / (float)BT;
}

extern "C" void kernel_launch(void* const* d_in, const int* in_sizes, int n_in,
                              void* d_out, int out_size) {
    const float* outputs      = (const float*)d_in[0]; // (8,100,3)
    const float* c2ws         = (const float*)d_in[1]; // (8,4,4)
    const float* scene_scales = (const float*)d_in[2]; // (8,)
    const float* means        = (const float*)d_in[3]; // (100000,3)
    const float* scales       = (const float*)d_in[4]; // (100000,3)
    float* out = (float*)d_out;

    kA<<<1, 1024>>>(outputs, c2ws, scene_scales);
    kB<<<(Nn + 255) / 256, 256>>>(means, scales);
    kC<<<NBLK, BT>>>();
    kD<<<1, 1024>>>(out);
}

// round 5
// speedup vs baseline: 1.3701x; 1.3701x over previous
#include <cuda_runtime.h>

#define Bn 8
#define Tn 100
#define BT 800
#define Nn 100000
#define NBLK 592
#define PER 169                 // ceil(Nn / NBLK); 592*169 = 100048
#define MARGINF 0.1f
#define THRESHF 0.5f
#define BIGV 1000000000.0f

// Zero-initialized device state. Invariant: every kernel_launch call begins
// AND ends with g_key2[] == 0 and g_done == 0 (last block resets them), so
// graph replays are deterministic. key2 = ~fkey(m); max(key2) <=> min(m);
// key2 == 0 means "never updated" (no inside point -> contribution 0).
__device__ unsigned int g_key2[BT];
__device__ unsigned int g_done;

__device__ __forceinline__ unsigned int fkey(float f) {
    unsigned int u = __float_as_uint(f);
    return (u & 0x80000000u) ? ~u : (u | 0x80000000u);
}
__device__ __forceinline__ float fdec(unsigned int k) {
    unsigned int u = (k & 0x80000000u) ? (k ^ 0x80000000u) : ~k;
    return __uint_as_float(u);
}

__global__ void __launch_bounds__(BT, 2) kMain(
    const float* __restrict__ outputs,      // (8,100,3)
    const float* __restrict__ c2ws,         // (8,4,4)
    const float* __restrict__ sscales,      // (8,)
    const float* __restrict__ means,        // (100000,3)
    const float* __restrict__ scales,       // (100000,3)
    float* __restrict__ out)
{
    extern __shared__ float4 s_list[];      // [Bn][PER]  {x,y,z,rad}, compacted
    __shared__ float s_r[BT * 3];           // 9600 B
    __shared__ float s_lo[Bn * 3], s_hi[Bn * 3];
    __shared__ int   s_cnt[Bn];
    __shared__ float s_part[32];
    __shared__ int   s_last;

    const int tid = threadIdx.x;
    const int b   = tid / Tn;

    // ---- prologue: retrajs (each thread its own bt) -------------------
    {
        float ssb = sscales[b];
        float o0 = outputs[tid * 3 + 0];
        float o1 = outputs[tid * 3 + 1];
        float o2 = outputs[tid * 3 + 2];
        const float* c = c2ws + b * 16;
#pragma unroll
        for (int e = 0; e < 3; e++) {
            float dot = o0 * c[e * 4 + 0] + o1 * c[e * 4 + 1] + o2 * c[e * 4 + 2];
            s_r[tid * 3 + e] = fmaf(ssb, dot, c[e * 4 + 3]);
        }
    }
    if (tid < Bn) s_cnt[tid] = 0;
    __syncthreads();

    // ---- per-b bounding boxes (24 threads, 100-iter serial) -----------
    if (tid < Bn * 3) {
        int bb = tid / 3, e = tid % 3;
        float lo = 3.4e38f, hi = -3.4e38f;
        for (int t = 0; t < Tn; t++) {
            float v = s_r[(bb * Tn + t) * 3 + e];
            lo = fminf(lo, v); hi = fmaxf(hi, v);
        }
        float thres = THRESHF * sscales[0];
        s_lo[tid] = lo - thres;
        s_hi[tid] = hi + thres;
    }
    __syncthreads();

    // ---- stage block's point slice, compacted per-b (warp-aggregated) -
    {
        int n0 = blockIdx.x * PER;
        int cnt_here = min(Nn - n0, PER);          // <= 169 < BT: single pass
        bool act = tid < cnt_here;
        float mx = 0.f, my = 0.f, mz = 0.f, rad = 0.f;
        if (act) {
            int n = n0 + tid;
            mx = means[n * 3 + 0]; my = means[n * 3 + 1]; mz = means[n * 3 + 2];
            float a0 = scales[n * 3 + 0], a1 = scales[n * 3 + 1], a2 = scales[n * 3 + 2];
            rad = fmaxf(a0, fmaxf(a1, a2));
        }
        unsigned lmask = (1u << (tid & 31)) - 1u;
#pragma unroll
        for (int bb = 0; bb < Bn; bb++) {
            bool in = act &&
                mx >= s_lo[bb * 3 + 0] && mx <= s_hi[bb * 3 + 0] &&
                my >= s_lo[bb * 3 + 1] && my <= s_hi[bb * 3 + 1] &&
                mz >= s_lo[bb * 3 + 2] && mz <= s_hi[bb * 3 + 2];
            unsigned bal = __ballot_sync(0xffffffffu, in);
            if (bal) {
                int leader = __ffs(bal) - 1;
                int base = 0;
                if ((tid & 31) == leader) base = atomicAdd(&s_cnt[bb], __popc(bal));
                base = __shfl_sync(0xffffffffu, base, leader);
                if (in) s_list[bb * PER + base + __popc(bal & lmask)] =
                            make_float4(mx, my, mz, rad);
            }
        }
    }
    __syncthreads();

    // ---- main loop: thread bt scans only its b's inside-list ----------
    float m = BIGV;
    {
        float rx = s_r[tid * 3 + 0];
        float ry = s_r[tid * 3 + 1];
        float rz = s_r[tid * 3 + 2];
        const float4* lst = s_list + b * PER;
        int n = s_cnt[b];
#pragma unroll 4
        for (int i = 0; i < n; i++) {
            float4 p = lst[i];
            float dx = rx - p.x, dy = ry - p.y, dz = rz - p.z;
            float d2 = fmaf(dx, dx, fmaf(dy, dy, dz * dz));
            float d;
            asm("sqrt.approx.f32 %0, %1;" : "=f"(d) : "f"(d2));
            m = fminf(m, d - p.w);
        }
    }
    if (m < BIGV) atomicMax(&g_key2[tid], ~fkey(m));

    // ---- grid-wide finalize via last-block pattern ---------------------
    __threadfence();
    __syncthreads();
    if (tid == 0) s_last = (atomicAdd(&g_done, 1u) == (unsigned)(NBLK - 1));
    __syncthreads();
    if (s_last) {
        __threadfence();
        unsigned k2;
        asm volatile("ld.global.cg.u32 %0, [%1];" : "=r"(k2) : "l"(&g_key2[tid]));
        float v = (k2 == 0u) ? 0.f : fmaxf(0.f, MARGINF - fdec(~k2));
#pragma unroll
        for (int o = 16; o > 0; o >>= 1) v += __shfl_xor_sync(0xffffffffu, v, o);
        if ((tid & 31) == 0) s_part[tid >> 5] = v;
        __syncthreads();
        if (tid < 32) {
            float w = (tid < (BT / 32)) ? s_part[tid] : 0.f;
#pragma unroll
            for (int o = 16; o > 0; o >>= 1) w += __shfl_xor_sync(0xffffffffu, w, o);
            if (tid == 0) out[0] = w / (float)BT;
        }
        // reset state for the next replay (each thread owns its slot)
        g_key2[tid] = 0u;
        if (tid == 0) g_done = 0u;
    }
}

extern "C" void kernel_launch(void* const* d_in, const int* in_sizes, int n_in,
                              void* d_out, int out_size) {
    const float* outputs      = (const float*)d_in[0];
    const float* c2ws         = (const float*)d_in[1];
    const float* scene_scales = (const float*)d_in[2];
    const float* means        = (const float*)d_in[3];
    const float* scales       = (const float*)d_in[4];
    float* out = (float*)d_out;

    size_t smem = (size_t)Bn * PER * sizeof(float4);   // 21632 B dynamic
    kMain<<<NBLK, BT, smem>>>(outputs, c2ws, scene_scales, means, scales, out);
}